// round 5
// baseline (speedup 1.0000x reference)
#include <cuda_runtime.h>
#include <cstddef>

// self_inhibit: B=4096 rows, T=8192 timesteps, scalar nonlinear recurrence per row.
// outputs (each B*T fp32, concatenated): v, s, inh, v_clamp(=v-s), x(copy of input)
//
// Single smem tile: x is loaded into smem (for the transposed serial read) AND
// retained in registers (for the flush, whose thread mapping equals the load's).
// The serial loop overwrites x with v in place. Flush reconstructs:
//   inh[t]   = decay*(x[t]-v[t]) + relu(v[t]-V_TH)
//   s[t]     = sigmoid(scale*(v[t]-V_TH) + b)
//   clamp[t] = v[t] - s[t]

constexpr int B_DIM  = 4096;
constexpr int T_DIM  = 8192;
constexpr int ROWS   = 128;    // rows per block == threads per block
constexpr int TS     = 32;     // time sub-tile (one full 128B line per row)
constexpr int TPAD   = 33;     // odd stride -> conflict-free banks
constexpr int CHUNK  = 256;    // time chunk per block
constexpr int WARM   = 64;     // speculative warm-up (validated: rel_err ~3e-8)
constexpr float V_TH = 1.27f;

__global__ __launch_bounds__(ROWS, 8)
void self_inhibit_kernel(const float* __restrict__ x,
                         const float* __restrict__ p_decay,
                         const float* __restrict__ p_scale,
                         const float* __restrict__ p_b,
                         float* __restrict__ out)
{
    __shared__ float sm[ROWS * TPAD];   // holds x, overwritten in place by v

    const int r    = threadIdx.x;
    const int row0 = blockIdx.x * ROWS;
    const int t0   = blockIdx.y * CHUNK;

    const float decay = *p_decay;
    const float scale = *p_scale;
    const float bb    = *p_b;

    const size_t BT = (size_t)B_DIM * (size_t)T_DIM;

    float inh = 0.0f;

    // ---- speculative warm-up (2 tiles; recurrence is strongly contractive) ----
    {
        int tw = t0 - WARM;
        if (tw < 0) tw = 0;
        for (int tb = tw; tb < t0; tb += TS) {
            __syncthreads();
            #pragma unroll
            for (int j = 0; j < 8; ++j) {
                int f   = r + j * ROWS;       // 0..1023
                int row = f >> 3;             // 8 lanes cover one row's 128B
                int c4  = (f & 7) * 4;
                float4 v4 = __ldcs((const float4*)(x + (size_t)(row0 + row) * T_DIM + tb + c4));
                float* p = &sm[row * TPAD + c4];
                p[0] = v4.x; p[1] = v4.y; p[2] = v4.z; p[3] = v4.w;
            }
            __syncthreads();
            #pragma unroll
            for (int tt = 0; tt < TS; ++tt) {
                float v    = sm[r * TPAD + tt] - inh;
                float over = v - V_TH;
                inh = fmaf(decay, inh, fmaxf(over, 0.0f));
            }
        }
    }

    // ---- owned chunk ----
    for (int tb = t0; tb < t0 + CHUNK; tb += TS) {
        __syncthreads();   // previous tile's flush readers done

        float4 xr[8];      // retained copy of this thread's x for the flush
        #pragma unroll
        for (int j = 0; j < 8; ++j) {
            int f   = r + j * ROWS;
            int row = f >> 3;
            int c4  = (f & 7) * 4;
            xr[j] = __ldcs((const float4*)(x + (size_t)(row0 + row) * T_DIM + tb + c4));
            float* p = &sm[row * TPAD + c4];
            p[0] = xr[j].x; p[1] = xr[j].y; p[2] = xr[j].z; p[3] = xr[j].w;
        }
        __syncthreads();

        // serial recurrence: thread r owns row r; v overwrites x in place
        #pragma unroll
        for (int tt = 0; tt < TS; ++tt) {
            float v    = sm[r * TPAD + tt] - inh;
            float over = v - V_TH;
            inh        = fmaf(decay, inh, fmaxf(over, 0.0f));
            sm[r * TPAD + tt] = v;
        }
        __syncthreads();

        // merged flush of all 5 planes; each warp STG.128 = 4 full 128B lines
        #pragma unroll
        for (int j = 0; j < 8; ++j) {
            int f   = r + j * ROWS;
            int row = f >> 3;
            int c4  = (f & 7) * 4;
            const float* pv = &sm[row * TPAD + c4];
            float4 v4 = make_float4(pv[0], pv[1], pv[2], pv[3]);
            float4 x4 = xr[j];

            float4 i4, s4, c4v;
            #pragma unroll
            for (int e = 0; e < 4; ++e) {
                float xv   = (&x4.x)[e];
                float v    = (&v4.x)[e];
                float over = v - V_TH;
                float rl   = fmaxf(over, 0.0f);
                (&i4.x)[e] = fmaf(decay, xv - v, rl);
                float z    = fmaf(scale, over, bb);
                float sg   = __fdividef(1.0f, 1.0f + __expf(-z));
                (&s4.x)[e] = sg;
                (&c4v.x)[e] = v - sg;
            }

            size_t g = (size_t)(row0 + row) * T_DIM + (size_t)(tb + c4);
            __stcs((float4*)(out + g),          v4);   // v_rec
            __stcs((float4*)(out + BT + g),     s4);   // s_rec
            __stcs((float4*)(out + 2 * BT + g), i4);   // inh_rec
            __stcs((float4*)(out + 3 * BT + g), c4v);  // v_rec_clamp
            __stcs((float4*)(out + 4 * BT + g), x4);   // x
        }
    }
}

extern "C" void kernel_launch(void* const* d_in, const int* in_sizes, int n_in,
                              void* d_out, int out_size)
{
    const float* x     = (const float*)d_in[0];
    const float* dec   = (const float*)d_in[1];
    const float* scale = (const float*)d_in[2];
    const float* b     = (const float*)d_in[3];
    float* out         = (float*)d_out;

    dim3 grid(B_DIM / ROWS, T_DIM / CHUNK);
    self_inhibit_kernel<<<grid, ROWS>>>(x, dec, scale, b, out);
}